// round 10
// baseline (speedup 1.0000x reference)
#include <cuda_runtime.h>

#define BB 8
#define NN 16384
#define DD 768
#define CC 8
#define NCLS 2
#define D4 (DD/4)               // 192 float4 per row
#define BAGBLK 37               // blocks per bag
#define NBLK (BB*BAGBLK)        // 296 = 2 * 148 SMs, one wave
#define NSEG (BB*CC)            // 64
#define BTH 768
#define GROUPS 8
#define GTH 96                  // threads per group; thread owns cols (c, c+96)
#define CHUNK 128               // rows per work item
#define CPB (NN/CHUNK)          // 128 chunks per bag
#define CW (CHUNK/32)           // 4 warps cover a chunk's labels
#define SLICE (CHUNK/GROUPS)    // 16 rows per group per chunk
#define KQ 4                    // k-split in reduce_head

// Scratch (device globals — allocation-free per harness rules)
__device__ float g_partials[NBLK * CC * DD];   // 7.3 MB
__device__ int   g_cntp[NBLK * CC];
__device__ float g_logits[NSEG * NCLS];
__device__ int   g_next[BB];                   // work counters (reset by reduce_head)

__global__ __launch_bounds__(BTH, 2)
void seg_sum_kernel(const float* __restrict__ inst, const int* __restrict__ labels) {
    __shared__ __align__(16) float s_acc[CC * DD];   // 24 KB, persists across chunks
    __shared__ int s_sorted[CHUNK];
    __shared__ int s_hist[CW][CC];
    __shared__ int s_off[CC + 1];
    __shared__ int s_cnt_tot[CC];
    __shared__ int s_chunk;

    const int t    = threadIdx.x;
    const int bag  = blockIdx.x % BB;
    const int slot = blockIdx.x / BB;            // 0..36 within bag
    const int g    = t / GTH;
    const int col  = t % GTH;

    for (int i = t; i < CC * DD; i += BTH) s_acc[i] = 0.0f;
    if (t < CC) s_cnt_tot[t] = 0;

    const float4* __restrict__ bag4 =
        reinterpret_cast<const float4*>(inst) + (long)bag * NN * D4;
    const int* __restrict__ blab = labels + (long)bag * NN;

    for (;;) {
        __syncthreads();                         // protect s_sorted/s_off reuse + s_acc init
        if (t == 0) s_chunk = atomicAdd(&g_next[bag], 1);
        if (t < CW * CC) ((int*)s_hist)[t] = 0;
        __syncthreads();
        const int ck = s_chunk;
        if (ck >= CPB) break;
        const int r0g = ck * CHUNK;              // row offset within bag

        // ---- deterministic counting sort of this chunk's labels ----
        int mylbl = -1, mypos = 0;
        const int myw = t >> 5;
        if (t < CHUNK) {
            mylbl = blab[r0g + t];
            unsigned mask = __match_any_sync(0xffffffffu, mylbl);
            int lane = t & 31;
            mypos = __popc(mask & ((1u << lane) - 1u));
            if (lane == (__ffs(mask) - 1))
                s_hist[myw][mylbl] = __popc(mask);
        }
        __syncthreads();
        if (t == 0) {
            int run = 0;
            #pragma unroll
            for (int l = 0; l < CC; ++l) {
                int c = 0;
                #pragma unroll
                for (int w = 0; w < CW; ++w) c += s_hist[w][l];
                s_off[l] = run;
                run += c;
                s_cnt_tot[l] += c;
            }
            s_off[CC] = run;                     // == CHUNK
        }
        __syncthreads();
        if (mylbl >= 0) {
            int base = s_off[mylbl];
            #pragma unroll
            for (int w = 0; w < CW; ++w)
                if (w < myw) base += s_hist[w][mylbl];
            s_sorted[base + mypos] = r0g + t;    // bag-row index
        }
        __syncthreads();

        // ---- hot loop: group walks its contiguous slice of the sorted chunk ----
        const int p0 = SLICE * g;
        const int p1 = SLICE * (g + 1);

        #pragma unroll
        for (int l = 0; l < CC; ++l) {
            int s = s_off[l]     > p0 ? s_off[l]     : p0;
            int e = s_off[l + 1] < p1 ? s_off[l + 1] : p1;
            if (s >= e) continue;

            float4 a0 = make_float4(0.f, 0.f, 0.f, 0.f);
            float4 a1 = make_float4(0.f, 0.f, 0.f, 0.f);
            int j = s;
            for (; j + 2 <= e; j += 2) {         // 4 LDG.128 in flight / thread
                int r0 = s_sorted[j];
                int r1 = s_sorted[j + 1];
                float4 v0 = __ldcs(&bag4[(long)r0 * D4 + col]);
                float4 w0 = __ldcs(&bag4[(long)r0 * D4 + col + GTH]);
                float4 v1 = __ldcs(&bag4[(long)r1 * D4 + col]);
                float4 w1 = __ldcs(&bag4[(long)r1 * D4 + col + GTH]);
                a0.x += v0.x; a0.y += v0.y; a0.z += v0.z; a0.w += v0.w;
                a1.x += w0.x; a1.y += w0.y; a1.z += w0.z; a1.w += w0.w;
                a0.x += v1.x; a0.y += v1.y; a0.z += v1.z; a0.w += v1.w;
                a1.x += w1.x; a1.y += w1.y; a1.z += w1.z; a1.w += w1.w;
            }
            if (j < e) {
                int r = s_sorted[j];
                float4 v = __ldcs(&bag4[(long)r * D4 + col]);
                float4 w = __ldcs(&bag4[(long)r * D4 + col + GTH]);
                a0.x += v.x; a0.y += v.y; a0.z += v.z; a0.w += v.w;
                a1.x += w.x; a1.y += w.y; a1.z += w.z; a1.w += w.w;
            }
            float* d0 = &s_acc[l * DD + col * 4];
            float* d1 = &s_acc[l * DD + (col + GTH) * 4];
            atomicAdd(d0 + 0, a0.x); atomicAdd(d0 + 1, a0.y);
            atomicAdd(d0 + 2, a0.z); atomicAdd(d0 + 3, a0.w);
            atomicAdd(d1 + 0, a1.x); atomicAdd(d1 + 1, a1.y);
            atomicAdd(d1 + 2, a1.z); atomicAdd(d1 + 3, a1.w);
        }
    }
    __syncthreads();

    // ---- write block partials once (plain stores) ----
    const int pslot = bag * BAGBLK + slot;       // layout matches reduce_head
    float4* part = reinterpret_cast<float4*>(g_partials) + (long)pslot * CC * D4;
    const float4* sa = reinterpret_cast<const float4*>(s_acc);
    for (int i = t; i < CC * D4; i += BTH) part[i] = sa[i];
    if (t < CC) g_cntp[pslot * CC + t] = s_cnt_tot[t];
}

// One block per segment, 768 threads: 4-way k-split over 37 partials,
// then dot with head_w. Also resets the work counters for next replay.
__global__ __launch_bounds__(KQ * D4)
void reduce_head_kernel(const float* __restrict__ head_w,
                        const float* __restrict__ head_b) {
    const int seg = blockIdx.x;
    const int bag = seg / CC, c = seg % CC;
    const int t   = threadIdx.x;
    const int col = t % D4;                 // float4 column
    const int q   = t / D4;                 // k-quarter 0..3

    __shared__ __align__(16) float4 s_q[KQ][D4];
    __shared__ float s_part[D4 / 32][2];
    __shared__ int   s_c[BAGBLK];

    if (t == 0 && seg < BB) g_next[seg] = 0;     // reset work counter
    if (t < BAGBLK) s_c[t] = g_cntp[(bag * BAGBLK + t) * CC + c];

    const int k0 = (BAGBLK * q) / KQ;
    const int k1 = (BAGBLK * (q + 1)) / KQ;
    const float4* src = reinterpret_cast<const float4*>(g_partials)
                        + ((long)(bag * BAGBLK) * CC + c) * D4 + col;
    float4 acc = make_float4(0.f, 0.f, 0.f, 0.f);
    #pragma unroll 5
    for (int k = k0; k < k1; ++k) {
        float4 v = src[(long)k * CC * D4];
        acc.x += v.x; acc.y += v.y; acc.z += v.z; acc.w += v.w;
    }
    s_q[q][col] = acc;
    __syncthreads();

    if (t < D4) {
        float4 a0 = s_q[0][col], a1 = s_q[1][col], a2 = s_q[2][col], a3 = s_q[3][col];
        acc.x = (a0.x + a1.x) + (a2.x + a3.x);
        acc.y = (a0.y + a1.y) + (a2.y + a3.y);
        acc.z = (a0.z + a1.z) + (a2.z + a3.z);
        acc.w = (a0.w + a1.w) + (a2.w + a3.w);

        float4 w0 = reinterpret_cast<const float4*>(head_w)[col];
        float4 w1 = reinterpret_cast<const float4*>(head_w)[D4 + col];
        float l0 = acc.x * w0.x + acc.y * w0.y + acc.z * w0.z + acc.w * w0.w;
        float l1 = acc.x * w1.x + acc.y * w1.y + acc.z * w1.z + acc.w * w1.w;
        #pragma unroll
        for (int o = 16; o > 0; o >>= 1) {
            l0 += __shfl_xor_sync(0xffffffff, l0, o);
            l1 += __shfl_xor_sync(0xffffffff, l1, o);
        }
        if ((t & 31) == 0) { s_part[t >> 5][0] = l0; s_part[t >> 5][1] = l1; }
    }
    __syncthreads();

    if (t == 0) {
        float L0 = 0.f, L1 = 0.f;
        #pragma unroll
        for (int i = 0; i < D4 / 32; ++i) { L0 += s_part[i][0]; L1 += s_part[i][1]; }
        int cnt = 0;
        #pragma unroll
        for (int k = 0; k < BAGBLK; ++k) cnt += s_c[k];
        float inv = 1.0f / (float)(cnt > 0 ? cnt : 1);
        g_logits[seg * NCLS + 0] = L0 * inv + head_b[0];
        g_logits[seg * NCLS + 1] = L1 * inv + head_b[1];
    }
}

__global__ void final_kernel(float* __restrict__ out) {
    int t = threadIdx.x;
    if (t < BB) {
        float best = -1e30f, bl0 = 0.f, bl1 = 0.f;
        #pragma unroll
        for (int c = 0; c < CC; ++c) {
            float l0 = g_logits[(t * CC + c) * NCLS + 0];
            float l1 = g_logits[(t * CC + c) * NCLS + 1];
            float m  = fmaxf(l0, l1);
            float e0 = expf(l0 - m), e1 = expf(l1 - m);
            float score = 1.0f - e0 / (e0 + e1);       // 1 - p[nor_index=0]
            if (score > best) { best = score; bl0 = l0; bl1 = l1; }
        }
        out[t * NCLS + 0] = bl0;
        out[t * NCLS + 1] = bl1;
    }
}

extern "C" void kernel_launch(void* const* d_in, const int* in_sizes, int n_in,
                              void* d_out, int out_size) {
    const float* inst_feat = (const float*)d_in[0];   // [B, N, D] f32
    const int*   labels    = (const int*)  d_in[1];   // [B, N] i32
    const float* head_w    = (const float*)d_in[2];   // [NC, D] f32
    const float* head_b    = (const float*)d_in[3];   // [NC] f32
    float* out = (float*)d_out;                       // [B, NC] f32

    seg_sum_kernel<<<NBLK, BTH>>>(inst_feat, labels);
    reduce_head_kernel<<<NSEG, KQ * D4>>>(head_w, head_b);
    final_kernel<<<1, 32>>>(out);
}

// round 11
// speedup vs baseline: 1.0687x; 1.0687x over previous
#include <cuda_runtime.h>

#define BB 8
#define NN 16384
#define DD 768
#define CC 8
#define NCLS 2
#define D4 (DD/4)               // 192 float4 per row
#define BPB 37                  // blocks per bag
#define NBLK (BB*BPB)           // 296 = 2 * 148 SMs, exactly one wave
#define NSEG (BB*CC)            // 64
#define BTH 768
#define GROUPS 8
#define GTH 96                  // threads per group; thread owns cols (c, c+96)
#define RBASE (NN/BPB)          // 442
#define REXTRA (NN - RBASE*BPB) // 30 blocks get 443
#define RMAX 448
#define NW 14                   // warps covering RMAX rows

// Scratch (device globals — allocation-free per harness rules)
__device__ float g_plog[NBLK * CC * NCLS];   // per-block per-cluster logit partials (19 KB)
__device__ int   g_cntp[NBLK * CC];

__global__ __launch_bounds__(BTH, 2)
void seg_sum_kernel(const float* __restrict__ inst, const int* __restrict__ labels,
                    const float* __restrict__ head_w) {
    // s_acc first and explicitly 16B-aligned: it is accessed as float4.
    __shared__ __align__(16) float s_acc[CC * DD];   // 24 KB
    __shared__ int   s_sorted[RMAX];
    __shared__ int   s_hist[NW][CC];
    __shared__ int   s_off[CC + 1];
    __shared__ int   s_cnt[CC];
    __shared__ float s_dot[GROUPS][GTH/32][NCLS];    // per-group per-warp dot partials

    const int t   = threadIdx.x;
    const int bag = blockIdx.x / BPB;
    const int bi  = blockIdx.x % BPB;
    const int rstart = bi * RBASE + (bi < REXTRA ? bi : REXTRA);
    const int R      = RBASE + (bi < REXTRA ? 1 : 0);       // 442 or 443

    // ---- zero ----
    if (t < NW * CC) ((int*)s_hist)[t] = 0;
    for (int i = t; i < CC * DD; i += BTH) s_acc[i] = 0.0f;
    __syncthreads();

    // ---- deterministic counting sort of row indices by label ----
    int mylbl = -1, mypos = 0, myw = t >> 5;
    if (t < NW * 32) {
        mylbl = (t < R) ? labels[(long)bag * NN + rstart + t] : -1;
        unsigned mask = __match_any_sync(0xffffffffu, mylbl);
        int lane = t & 31;
        mypos = __popc(mask & ((1u << lane) - 1u));
        if (mylbl >= 0 && lane == (__ffs(mask) - 1))
            s_hist[myw][mylbl] = __popc(mask);
    }
    __syncthreads();
    if (t == 0) {
        int run = 0;
        #pragma unroll
        for (int l = 0; l < CC; ++l) {
            int c = 0;
            #pragma unroll
            for (int w = 0; w < NW; ++w) c += s_hist[w][l];
            s_cnt[l] = c;
            s_off[l] = run;
            run += c;
        }
        s_off[CC] = run;
    }
    __syncthreads();
    if (mylbl >= 0) {
        int base = s_off[mylbl];
        #pragma unroll
        for (int w = 0; w < NW; ++w)
            if (w < myw) base += s_hist[w][mylbl];
        s_sorted[base + mypos] = t;             // local row index
    }
    __syncthreads();

    // ---- hot loop: each group walks a contiguous slice of the sorted list ----
    const int g   = t / GTH;
    const int col = t % GTH;
    const int p0  = (R * g) / GROUPS;
    const int p1  = (R * (g + 1)) / GROUPS;

    const float4* __restrict__ base4 =
        reinterpret_cast<const float4*>(inst) + ((long)bag * NN + rstart) * D4;

    #pragma unroll
    for (int l = 0; l < CC; ++l) {
        int s = s_off[l]     > p0 ? s_off[l]     : p0;
        int e = s_off[l + 1] < p1 ? s_off[l + 1] : p1;
        if (s >= e) continue;

        float4 a0 = make_float4(0.f, 0.f, 0.f, 0.f);
        float4 a1 = make_float4(0.f, 0.f, 0.f, 0.f);
        int j = s;
        for (; j + 2 <= e; j += 2) {            // 4 LDG.128 in flight / thread
            int r0 = s_sorted[j];
            int r1 = s_sorted[j + 1];
            float4 v0 = __ldcs(&base4[(long)r0 * D4 + col]);
            float4 w0 = __ldcs(&base4[(long)r0 * D4 + col + GTH]);
            float4 v1 = __ldcs(&base4[(long)r1 * D4 + col]);
            float4 w1 = __ldcs(&base4[(long)r1 * D4 + col + GTH]);
            a0.x += v0.x; a0.y += v0.y; a0.z += v0.z; a0.w += v0.w;
            a1.x += w0.x; a1.y += w0.y; a1.z += w0.z; a1.w += w0.w;
            a0.x += v1.x; a0.y += v1.y; a0.z += v1.z; a0.w += v1.w;
            a1.x += w1.x; a1.y += w1.y; a1.z += w1.z; a1.w += w1.w;
        }
        if (j < e) {
            int r = s_sorted[j];
            float4 v = __ldcs(&base4[(long)r * D4 + col]);
            float4 w = __ldcs(&base4[(long)r * D4 + col + GTH]);
            a0.x += v.x; a0.y += v.y; a0.z += v.z; a0.w += v.w;
            a1.x += w.x; a1.y += w.y; a1.z += w.z; a1.w += w.w;
        }
        // flush run-partial (<= ~8 flushes per thread total)
        float* d0 = &s_acc[l * DD + col * 4];
        float* d1 = &s_acc[l * DD + (col + GTH) * 4];
        atomicAdd(d0 + 0, a0.x); atomicAdd(d0 + 1, a0.y);
        atomicAdd(d0 + 2, a0.z); atomicAdd(d0 + 3, a0.w);
        atomicAdd(d1 + 0, a1.x); atomicAdd(d1 + 1, a1.y);
        atomicAdd(d1 + 2, a1.z); atomicAdd(d1 + 3, a1.w);
    }
    __syncthreads();

    // ---- epilogue: dot block-partial sums with head_w -> 16 floats ----
    // logits are linear in the segment sum, so per-block dot partials suffice.
    {
        const float4* sa = reinterpret_cast<const float4*>(s_acc);
        const float4* W  = reinterpret_cast<const float4*>(head_w);
        float4 a0 = sa[g * D4 + col];
        float4 a1 = sa[g * D4 + col + GTH];
        float4 u0 = W[col],      u1 = W[col + GTH];        // class 0 row
        float4 v0 = W[D4 + col], v1 = W[D4 + col + GTH];   // class 1 row
        float l0 = a0.x*u0.x + a0.y*u0.y + a0.z*u0.z + a0.w*u0.w
                 + a1.x*u1.x + a1.y*u1.y + a1.z*u1.z + a1.w*u1.w;
        float l1 = a0.x*v0.x + a0.y*v0.y + a0.z*v0.z + a0.w*v0.w
                 + a1.x*v1.x + a1.y*v1.y + a1.z*v1.z + a1.w*v1.w;
        #pragma unroll
        for (int o = 16; o > 0; o >>= 1) {
            l0 += __shfl_xor_sync(0xffffffff, l0, o);
            l1 += __shfl_xor_sync(0xffffffff, l1, o);
        }
        if ((col & 31) == 0) {
            s_dot[g][col >> 5][0] = l0;
            s_dot[g][col >> 5][1] = l1;
        }
    }
    __syncthreads();
    if (t < CC * NCLS) {                         // 16 threads write logit partials
        int gg = t >> 1, cls = t & 1;
        float s = s_dot[gg][0][cls] + s_dot[gg][1][cls] + s_dot[gg][2][cls];
        g_plog[(blockIdx.x * CC + gg) * NCLS + cls] = s;
    }
    if (t < CC) g_cntp[blockIdx.x * CC + t] = s_cnt[t];
}

// Single small kernel: reduce 37 logit-partials + counts per segment,
// then softmax/argmax/gather per bag.
__global__ __launch_bounds__(256)
void finalize_kernel(const float* __restrict__ head_b, float* __restrict__ out) {
    __shared__ float s_logits[NSEG][NCLS];
    __shared__ int   s_cnt[NSEG];
    const int t = threadIdx.x;

    if (t < NSEG * NCLS) {                       // 128 threads: one (seg, cls) each
        int seg = t >> 1, cls = t & 1;
        int bag = seg / CC, c = seg % CC;
        float acc = 0.0f;
        #pragma unroll 4
        for (int k = 0; k < BPB; ++k)
            acc += g_plog[((bag * BPB + k) * CC + c) * NCLS + cls];
        s_logits[seg][cls] = acc;                // divide by cnt later
    } else if (t < NSEG * NCLS + NSEG) {         // 64 threads: one segment count each
        int seg = t - NSEG * NCLS;
        int bag = seg / CC, c = seg % CC;
        int cnt = 0;
        #pragma unroll 4
        for (int k = 0; k < BPB; ++k)
            cnt += g_cntp[(bag * BPB + k) * CC + c];
        s_cnt[seg] = cnt;
    }
    __syncthreads();

    if (t < NSEG * NCLS) {                       // apply mean + bias
        int seg = t >> 1, cls = t & 1;
        int cnt = s_cnt[seg];
        float inv = 1.0f / (float)(cnt > 0 ? cnt : 1);
        s_logits[seg][cls] = s_logits[seg][cls] * inv + head_b[cls];
    }
    __syncthreads();

    if (t < BB) {
        float best = -1e30f, bl0 = 0.f, bl1 = 0.f;
        #pragma unroll
        for (int c = 0; c < CC; ++c) {
            float l0 = s_logits[t * CC + c][0];
            float l1 = s_logits[t * CC + c][1];
            float m  = fmaxf(l0, l1);
            float e0 = expf(l0 - m), e1 = expf(l1 - m);
            float score = 1.0f - e0 / (e0 + e1);       // 1 - p[nor_index=0]
            if (score > best) { best = score; bl0 = l0; bl1 = l1; }
        }
        out[t * NCLS + 0] = bl0;
        out[t * NCLS + 1] = bl1;
    }
}

extern "C" void kernel_launch(void* const* d_in, const int* in_sizes, int n_in,
                              void* d_out, int out_size) {
    const float* inst_feat = (const float*)d_in[0];   // [B, N, D] f32
    const int*   labels    = (const int*)  d_in[1];   // [B, N] i32
    const float* head_w    = (const float*)d_in[2];   // [NC, D] f32
    const float* head_b    = (const float*)d_in[3];   // [NC] f32
    float* out = (float*)d_out;                       // [B, NC] f32

    seg_sum_kernel<<<NBLK, BTH>>>(inst_feat, labels, head_w);
    finalize_kernel<<<1, 256>>>(head_b, out);
}

// round 12
// speedup vs baseline: 1.1033x; 1.0324x over previous
#include <cuda_runtime.h>

#define BB 8
#define NN 16384
#define DD 768
#define CC 8
#define NCLS 2
#define D4 (DD/4)               // 192 float4 per row
#define BPB 37                  // blocks per bag
#define NBLK (BB*BPB)           // 296 = 2 * 148 SMs, exactly one wave
#define NSEG (BB*CC)            // 64
#define BTH 768
#define GROUPS 8
#define GTH 96                  // threads per group; thread owns cols (c, c+96)
#define RBASE (NN/BPB)          // 442
#define REXTRA (NN - RBASE*BPB) // 30 blocks get 443
#define RMAX 448
#define NW 14                   // warps covering RMAX rows

// Scratch (device globals — allocation-free per harness rules)
__device__ float g_plog[NBLK * CC * NCLS];   // per-block per-cluster logit partials
__device__ int   g_cntp[NBLK * CC];

__global__ __launch_bounds__(BTH, 2)
void seg_sum_kernel(const float* __restrict__ inst, const int* __restrict__ labels,
                    const float* __restrict__ head_w) {
    // s_acc first and explicitly 16B-aligned: it is accessed as float4.
    __shared__ __align__(16) float s_acc[CC * DD];   // 24 KB
    __shared__ int   s_sorted[RMAX];
    __shared__ int   s_hist[NW][CC];
    __shared__ int   s_off[CC + 1];
    __shared__ int   s_cnt[CC];
    __shared__ float s_dot[GROUPS][GTH/32][NCLS];    // per-group per-warp dot partials

    const int t   = threadIdx.x;
    const int bag = blockIdx.x / BPB;
    const int bi  = blockIdx.x % BPB;
    const int rstart = bi * RBASE + (bi < REXTRA ? bi : REXTRA);
    const int R      = RBASE + (bi < REXTRA ? 1 : 0);       // 442 or 443

    // ---- zero ----
    if (t < NW * CC) ((int*)s_hist)[t] = 0;
    for (int i = t; i < CC * DD; i += BTH) s_acc[i] = 0.0f;
    __syncthreads();

    // ---- deterministic counting sort of row indices by label ----
    int mylbl = -1, mypos = 0, myw = t >> 5;
    if (t < NW * 32) {
        mylbl = (t < R) ? labels[(long)bag * NN + rstart + t] : -1;
        unsigned mask = __match_any_sync(0xffffffffu, mylbl);
        int lane = t & 31;
        mypos = __popc(mask & ((1u << lane) - 1u));
        if (mylbl >= 0 && lane == (__ffs(mask) - 1))
            s_hist[myw][mylbl] = __popc(mask);
    }
    __syncthreads();
    if (t == 0) {
        int run = 0;
        #pragma unroll
        for (int l = 0; l < CC; ++l) {
            int c = 0;
            #pragma unroll
            for (int w = 0; w < NW; ++w) c += s_hist[w][l];
            s_cnt[l] = c;
            s_off[l] = run;
            run += c;
        }
        s_off[CC] = run;
    }
    __syncthreads();
    if (mylbl >= 0) {
        int base = s_off[mylbl];
        #pragma unroll
        for (int w = 0; w < NW; ++w)
            if (w < myw) base += s_hist[w][mylbl];
        s_sorted[base + mypos] = t;             // local row index
    }
    __syncthreads();

    // ---- hot loop: each group walks a contiguous slice of the sorted list ----
    const int g   = t / GTH;
    const int col = t % GTH;
    const int p0  = (R * g) / GROUPS;
    const int p1  = (R * (g + 1)) / GROUPS;

    const float4* __restrict__ base4 =
        reinterpret_cast<const float4*>(inst) + ((long)bag * NN + rstart) * D4;

    #pragma unroll
    for (int l = 0; l < CC; ++l) {
        int s = s_off[l]     > p0 ? s_off[l]     : p0;
        int e = s_off[l + 1] < p1 ? s_off[l + 1] : p1;
        if (s >= e) continue;

        float4 a0 = make_float4(0.f, 0.f, 0.f, 0.f);
        float4 a1 = make_float4(0.f, 0.f, 0.f, 0.f);
        int j = s;
        for (; j + 2 <= e; j += 2) {            // 4 LDG.128 in flight / thread
            int r0 = s_sorted[j];
            int r1 = s_sorted[j + 1];
            float4 v0 = __ldcs(&base4[(long)r0 * D4 + col]);
            float4 w0 = __ldcs(&base4[(long)r0 * D4 + col + GTH]);
            float4 v1 = __ldcs(&base4[(long)r1 * D4 + col]);
            float4 w1 = __ldcs(&base4[(long)r1 * D4 + col + GTH]);
            a0.x += v0.x; a0.y += v0.y; a0.z += v0.z; a0.w += v0.w;
            a1.x += w0.x; a1.y += w0.y; a1.z += w0.z; a1.w += w0.w;
            a0.x += v1.x; a0.y += v1.y; a0.z += v1.z; a0.w += v1.w;
            a1.x += w1.x; a1.y += w1.y; a1.z += w1.z; a1.w += w1.w;
        }
        if (j < e) {
            int r = s_sorted[j];
            float4 v = __ldcs(&base4[(long)r * D4 + col]);
            float4 w = __ldcs(&base4[(long)r * D4 + col + GTH]);
            a0.x += v.x; a0.y += v.y; a0.z += v.z; a0.w += v.w;
            a1.x += w.x; a1.y += w.y; a1.z += w.z; a1.w += w.w;
        }
        // flush run-partial (<= ~8 flushes per thread total)
        float* d0 = &s_acc[l * DD + col * 4];
        float* d1 = &s_acc[l * DD + (col + GTH) * 4];
        atomicAdd(d0 + 0, a0.x); atomicAdd(d0 + 1, a0.y);
        atomicAdd(d0 + 2, a0.z); atomicAdd(d0 + 3, a0.w);
        atomicAdd(d1 + 0, a1.x); atomicAdd(d1 + 1, a1.y);
        atomicAdd(d1 + 2, a1.z); atomicAdd(d1 + 3, a1.w);
    }
    __syncthreads();

    // ---- epilogue: dot block-partial sums with head_w -> 16 floats ----
    {
        const float4* sa = reinterpret_cast<const float4*>(s_acc);
        const float4* W  = reinterpret_cast<const float4*>(head_w);
        float4 a0 = sa[g * D4 + col];
        float4 a1 = sa[g * D4 + col + GTH];
        float4 u0 = W[col],      u1 = W[col + GTH];        // class 0 row
        float4 v0 = W[D4 + col], v1 = W[D4 + col + GTH];   // class 1 row
        float l0 = a0.x*u0.x + a0.y*u0.y + a0.z*u0.z + a0.w*u0.w
                 + a1.x*u1.x + a1.y*u1.y + a1.z*u1.z + a1.w*u1.w;
        float l1 = a0.x*v0.x + a0.y*v0.y + a0.z*v0.z + a0.w*v0.w
                 + a1.x*v1.x + a1.y*v1.y + a1.z*v1.z + a1.w*v1.w;
        #pragma unroll
        for (int o = 16; o > 0; o >>= 1) {
            l0 += __shfl_xor_sync(0xffffffff, l0, o);
            l1 += __shfl_xor_sync(0xffffffff, l1, o);
        }
        if ((col & 31) == 0) {
            s_dot[g][col >> 5][0] = l0;
            s_dot[g][col >> 5][1] = l1;
        }
    }
    __syncthreads();
    if (t < CC * NCLS) {                         // 16 threads write logit partials
        int gg = t >> 1, cls = t & 1;
        float s = s_dot[gg][0][cls] + s_dot[gg][1][cls] + s_dot[gg][2][cls];
        g_plog[(blockIdx.x * CC + gg) * NCLS + cls] = s;
    }
    if (t < CC) g_cntp[blockIdx.x * CC + t] = s_cnt[t];
}

// One block per bag: bulk-load this bag's partial logits/counts into smem
// (2-3 coalesced loads per thread), reduce, softmax/argmax, write 2 floats.
__global__ __launch_bounds__(256)
void finalize_kernel(const float* __restrict__ head_b, float* __restrict__ out) {
    const int bag = blockIdx.x;
    const int t   = threadIdx.x;

    __shared__ float s_pl[BPB * CC * NCLS];   // 592 floats
    __shared__ int   s_pc[BPB * CC];          // 296 ints
    __shared__ float s_logits[CC][NCLS];
    __shared__ int   s_cnt[CC];

    const float* plog = g_plog + (long)bag * BPB * CC * NCLS;
    const int*   cntp = g_cntp + (long)bag * BPB * CC;
    #pragma unroll
    for (int i = t; i < BPB * CC * NCLS; i += 256) s_pl[i] = plog[i];
    #pragma unroll
    for (int i = t; i < BPB * CC; i += 256) s_pc[i] = cntp[i];
    __syncthreads();

    if (t < CC * NCLS) {                       // 16 threads: one (cluster, class)
        int c = t >> 1, cls = t & 1;
        float acc = 0.0f;
        #pragma unroll
        for (int k = 0; k < BPB; ++k) acc += s_pl[(k * CC + c) * NCLS + cls];
        s_logits[c][cls] = acc;
    } else if (t >= 32 && t < 32 + CC) {       // 8 threads: one cluster count
        int c = t - 32;
        int cnt = 0;
        #pragma unroll
        for (int k = 0; k < BPB; ++k) cnt += s_pc[k * CC + c];
        s_cnt[c] = cnt;
    }
    __syncthreads();

    if (t == 0) {
        float best = -1e30f, bl0 = 0.f, bl1 = 0.f;
        #pragma unroll
        for (int c = 0; c < CC; ++c) {
            int cnt = s_cnt[c];
            float inv = 1.0f / (float)(cnt > 0 ? cnt : 1);
            float l0 = s_logits[c][0] * inv + head_b[0];
            float l1 = s_logits[c][1] * inv + head_b[1];
            float m  = fmaxf(l0, l1);
            float e0 = expf(l0 - m), e1 = expf(l1 - m);
            float score = 1.0f - e0 / (e0 + e1);       // 1 - p[nor_index=0]
            if (score > best) { best = score; bl0 = l0; bl1 = l1; }
        }
        out[bag * NCLS + 0] = bl0;
        out[bag * NCLS + 1] = bl1;
    }
}

extern "C" void kernel_launch(void* const* d_in, const int* in_sizes, int n_in,
                              void* d_out, int out_size) {
    const float* inst_feat = (const float*)d_in[0];   // [B, N, D] f32
    const int*   labels    = (const int*)  d_in[1];   // [B, N] i32
    const float* head_w    = (const float*)d_in[2];   // [NC, D] f32
    const float* head_b    = (const float*)d_in[3];   // [NC] f32
    float* out = (float*)d_out;                       // [B, NC] f32

    seg_sum_kernel<<<NBLK, BTH>>>(inst_feat, labels, head_w);
    finalize_kernel<<<BB, 256>>>(head_b, out);
}

// round 13
// speedup vs baseline: 1.1350x; 1.0287x over previous
#include <cuda_runtime.h>

#define BB 8
#define NN 16384
#define DD 768
#define CC 8
#define NCLS 2
#define D4 (DD/4)               // 192 float4 per row
#define BPB 37                  // blocks per bag
#define NBLK (BB*BPB)           // 296 = 2 * 148 SMs, exactly one wave
#define BTH 768
#define GROUPS 8
#define GTH 96                  // threads per group; thread owns cols (c, c+96)
#define RBASE (NN/BPB)          // 442
#define REXTRA (NN - RBASE*BPB) // 30 blocks get 443
#define RMAX 448
#define NW 14                   // warps covering RMAX rows

// Scratch (device globals — allocation-free per harness rules)
__device__ float g_plog[NBLK * CC * NCLS];   // per-block per-cluster logit partials
__device__ int   g_cntp[NBLK * CC];
__device__ int   g_bagdone[BB];              // per-bag completion counters (self-reset)

__global__ __launch_bounds__(BTH, 2)
void seg_sum_kernel(const float* __restrict__ inst, const int* __restrict__ labels,
                    const float* __restrict__ head_w, const float* __restrict__ head_b,
                    float* __restrict__ out) {
    // s_acc first and explicitly 16B-aligned: it is accessed as float4.
    __shared__ __align__(16) float s_acc[CC * DD];   // 24 KB
    __shared__ int   s_sorted[RMAX];
    __shared__ int   s_hist[NW][CC];
    __shared__ int   s_off[CC + 1];
    __shared__ int   s_cnt[CC];
    __shared__ float s_dot[GROUPS][GTH/32][NCLS];    // per-group per-warp dot partials
    __shared__ int   s_isLast;
    __shared__ float s_pl[BPB * CC * NCLS];          // last-block finalize buffers
    __shared__ int   s_pc[BPB * CC];
    __shared__ float s_logits[CC][NCLS];
    __shared__ int   s_ctot[CC];

    const int t   = threadIdx.x;
    const int bag = blockIdx.x / BPB;
    const int bi  = blockIdx.x % BPB;
    const int rstart = bi * RBASE + (bi < REXTRA ? bi : REXTRA);
    const int R      = RBASE + (bi < REXTRA ? 1 : 0);       // 442 or 443

    // ---- zero ----
    if (t < NW * CC) ((int*)s_hist)[t] = 0;
    for (int i = t; i < CC * DD; i += BTH) s_acc[i] = 0.0f;
    __syncthreads();

    // ---- deterministic counting sort of row indices by label ----
    int mylbl = -1, mypos = 0, myw = t >> 5;
    if (t < NW * 32) {
        mylbl = (t < R) ? labels[(long)bag * NN + rstart + t] : -1;
        unsigned mask = __match_any_sync(0xffffffffu, mylbl);
        int lane = t & 31;
        mypos = __popc(mask & ((1u << lane) - 1u));
        if (mylbl >= 0 && lane == (__ffs(mask) - 1))
            s_hist[myw][mylbl] = __popc(mask);
    }
    __syncthreads();
    if (t < CC) {                               // parallel column sums
        int c = 0;
        #pragma unroll
        for (int w = 0; w < NW; ++w) c += s_hist[w][t];
        s_cnt[t] = c;
    }
    __syncthreads();
    if (t == 0) {                               // short 8-step prefix
        int run = 0;
        #pragma unroll
        for (int l = 0; l < CC; ++l) { s_off[l] = run; run += s_cnt[l]; }
        s_off[CC] = run;
    }
    __syncthreads();
    if (mylbl >= 0) {
        int base = s_off[mylbl];
        #pragma unroll
        for (int w = 0; w < NW; ++w)
            if (w < myw) base += s_hist[w][mylbl];
        s_sorted[base + mypos] = t;             // local row index
    }
    __syncthreads();

    // ---- hot loop: each group walks a contiguous slice of the sorted list ----
    const int g   = t / GTH;
    const int col = t % GTH;
    const int p0  = (R * g) / GROUPS;
    const int p1  = (R * (g + 1)) / GROUPS;

    const float4* __restrict__ base4 =
        reinterpret_cast<const float4*>(inst) + ((long)bag * NN + rstart) * D4;

    #pragma unroll
    for (int l = 0; l < CC; ++l) {
        int s = s_off[l]     > p0 ? s_off[l]     : p0;
        int e = s_off[l + 1] < p1 ? s_off[l + 1] : p1;
        if (s >= e) continue;

        float4 a0 = make_float4(0.f, 0.f, 0.f, 0.f);
        float4 a1 = make_float4(0.f, 0.f, 0.f, 0.f);
        int j = s;
        for (; j + 2 <= e; j += 2) {            // 4 LDG.128 in flight / thread
            int r0 = s_sorted[j];
            int r1 = s_sorted[j + 1];
            float4 v0 = __ldcs(&base4[(long)r0 * D4 + col]);
            float4 w0 = __ldcs(&base4[(long)r0 * D4 + col + GTH]);
            float4 v1 = __ldcs(&base4[(long)r1 * D4 + col]);
            float4 w1 = __ldcs(&base4[(long)r1 * D4 + col + GTH]);
            a0.x += v0.x; a0.y += v0.y; a0.z += v0.z; a0.w += v0.w;
            a1.x += w0.x; a1.y += w0.y; a1.z += w0.z; a1.w += w0.w;
            a0.x += v1.x; a0.y += v1.y; a0.z += v1.z; a0.w += v1.w;
            a1.x += w1.x; a1.y += w1.y; a1.z += w1.z; a1.w += w1.w;
        }
        if (j < e) {
            int r = s_sorted[j];
            float4 v = __ldcs(&base4[(long)r * D4 + col]);
            float4 w = __ldcs(&base4[(long)r * D4 + col + GTH]);
            a0.x += v.x; a0.y += v.y; a0.z += v.z; a0.w += v.w;
            a1.x += w.x; a1.y += w.y; a1.z += w.z; a1.w += w.w;
        }
        // flush run-partial (<= ~8 flushes per thread total)
        float* d0 = &s_acc[l * DD + col * 4];
        float* d1 = &s_acc[l * DD + (col + GTH) * 4];
        atomicAdd(d0 + 0, a0.x); atomicAdd(d0 + 1, a0.y);
        atomicAdd(d0 + 2, a0.z); atomicAdd(d0 + 3, a0.w);
        atomicAdd(d1 + 0, a1.x); atomicAdd(d1 + 1, a1.y);
        atomicAdd(d1 + 2, a1.z); atomicAdd(d1 + 3, a1.w);
    }
    __syncthreads();

    // ---- epilogue: dot block-partial sums with head_w -> 16 floats ----
    {
        const float4* sa = reinterpret_cast<const float4*>(s_acc);
        const float4* W  = reinterpret_cast<const float4*>(head_w);
        float4 a0 = sa[g * D4 + col];
        float4 a1 = sa[g * D4 + col + GTH];
        float4 u0 = W[col],      u1 = W[col + GTH];        // class 0 row
        float4 v0 = W[D4 + col], v1 = W[D4 + col + GTH];   // class 1 row
        float l0 = a0.x*u0.x + a0.y*u0.y + a0.z*u0.z + a0.w*u0.w
                 + a1.x*u1.x + a1.y*u1.y + a1.z*u1.z + a1.w*u1.w;
        float l1 = a0.x*v0.x + a0.y*v0.y + a0.z*v0.z + a0.w*v0.w
                 + a1.x*v1.x + a1.y*v1.y + a1.z*v1.z + a1.w*v1.w;
        #pragma unroll
        for (int o = 16; o > 0; o >>= 1) {
            l0 += __shfl_xor_sync(0xffffffff, l0, o);
            l1 += __shfl_xor_sync(0xffffffff, l1, o);
        }
        if ((col & 31) == 0) {
            s_dot[g][col >> 5][0] = l0;
            s_dot[g][col >> 5][1] = l1;
        }
    }
    __syncthreads();
    if (t < CC * NCLS) {                         // 16 threads write logit partials
        int gg = t >> 1, cls = t & 1;
        float s = s_dot[gg][0][cls] + s_dot[gg][1][cls] + s_dot[gg][2][cls];
        g_plog[(blockIdx.x * CC + gg) * NCLS + cls] = s;
    }
    if (t < CC) g_cntp[blockIdx.x * CC + t] = s_cnt[t];

    // ---- last block per bag performs the finalize ----
    __threadfence();                             // publish this block's partials
    __syncthreads();                             // (cumulativity: all writers fenced-before)
    if (t == 0) {
        int old = atomicAdd(&g_bagdone[bag], 1);
        s_isLast = (old == BPB - 1) ? 1 : 0;
    }
    __syncthreads();

    if (s_isLast) {
        const float* plog = g_plog + (long)bag * BPB * CC * NCLS;
        const int*   cntp = g_cntp + (long)bag * BPB * CC;
        for (int i = t; i < BPB * CC * NCLS; i += BTH) s_pl[i] = __ldcg(&plog[i]);
        for (int i = t; i < BPB * CC; i += BTH)        s_pc[i] = __ldcg(&cntp[i]);
        __syncthreads();

        if (t < CC * NCLS) {                     // 16 threads: one (cluster, class)
            int c = t >> 1, cls = t & 1;
            float acc = 0.0f;
            #pragma unroll
            for (int k = 0; k < BPB; ++k) acc += s_pl[(k * CC + c) * NCLS + cls];
            s_logits[c][cls] = acc;
        } else if (t >= 32 && t < 32 + CC) {     // 8 threads: one cluster count
            int c = t - 32;
            int cnt = 0;
            #pragma unroll
            for (int k = 0; k < BPB; ++k) cnt += s_pc[k * CC + c];
            s_ctot[c] = cnt;
        }
        __syncthreads();

        if (t == 0) {
            float b0 = head_b[0], b1 = head_b[1];
            float best = -1e30f, bl0 = 0.f, bl1 = 0.f;
            #pragma unroll
            for (int c = 0; c < CC; ++c) {
                int cnt = s_ctot[c];
                float inv = 1.0f / (float)(cnt > 0 ? cnt : 1);
                float l0 = s_logits[c][0] * inv + b0;
                float l1 = s_logits[c][1] * inv + b1;
                float m  = fmaxf(l0, l1);
                float e0 = expf(l0 - m), e1 = expf(l1 - m);
                float score = 1.0f - e0 / (e0 + e1);   // 1 - p[nor_index=0]
                if (score > best) { best = score; bl0 = l0; bl1 = l1; }
            }
            out[bag * NCLS + 0] = bl0;
            out[bag * NCLS + 1] = bl1;
            g_bagdone[bag] = 0;                  // reset for next graph replay
        }
    }
}

extern "C" void kernel_launch(void* const* d_in, const int* in_sizes, int n_in,
                              void* d_out, int out_size) {
    const float* inst_feat = (const float*)d_in[0];   // [B, N, D] f32
    const int*   labels    = (const int*)  d_in[1];   // [B, N] i32
    const float* head_w    = (const float*)d_in[2];   // [NC, D] f32
    const float* head_b    = (const float*)d_in[3];   // [NC] f32
    float* out = (float*)d_out;                       // [B, NC] f32

    seg_sum_kernel<<<NBLK, BTH>>>(inst_feat, labels, head_w, head_b, out);
}

// round 14
// speedup vs baseline: 1.2446x; 1.0965x over previous
#include <cuda_runtime.h>

#define BB 8
#define NN 16384
#define DD 768
#define CC 8
#define NCLS 2
#define D4 (DD/4)               // 192 float4 per row
#define BPB 74                  // blocks per bag
#define NBLK (BB*BPB)           // 592 = 4 * 148 SMs, exactly one wave
#define BTH 384
#define GROUPS 4
#define GTH 96                  // threads per group; thread owns cols (c, c+96)
#define RBASE (NN/BPB)          // 221
#define REXTRA (NN - RBASE*BPB) // 30 blocks get 222
#define RMAX 224
#define NW 7                    // warps covering RMAX rows

// Scratch (device globals — allocation-free per harness rules)
__device__ float g_plog[NBLK * CC * NCLS];   // per-block per-cluster logit partials
__device__ int   g_cntp[NBLK * CC];
__device__ int   g_bagdone[BB];              // per-bag completion counters (self-reset)

__global__ __launch_bounds__(BTH, 4)
void seg_sum_kernel(const float* __restrict__ inst, const int* __restrict__ labels,
                    const float* __restrict__ head_w, const float* __restrict__ head_b,
                    float* __restrict__ out) {
    // s_acc first and explicitly 16B-aligned: it is accessed as float4.
    __shared__ __align__(16) float s_acc[CC * DD];   // 24 KB
    __shared__ int   s_sorted[RMAX];
    __shared__ int   s_hist[NW][CC];
    __shared__ int   s_off[CC + 1];
    __shared__ int   s_cnt[CC];
    __shared__ float s_dot[CC][GTH/32][NCLS];        // per-cluster per-warp dot partials
    __shared__ int   s_isLast;
    __shared__ float s_pl[BPB * CC * NCLS];          // last-block finalize buffers
    __shared__ int   s_pc[BPB * CC];
    __shared__ float s_logits[CC][NCLS];
    __shared__ int   s_ctot[CC];

    const int t   = threadIdx.x;
    const int bag = blockIdx.x / BPB;
    const int bi  = blockIdx.x % BPB;
    const int rstart = bi * RBASE + (bi < REXTRA ? bi : REXTRA);
    const int R      = RBASE + (bi < REXTRA ? 1 : 0);       // 221 or 222

    // ---- L2 prefetch of first 64 rows: fill DRAM during the sort bubble ----
    {
        const char* pf = (const char*)(inst + ((long)bag * NN + rstart) * DD);
        #pragma unroll
        for (int k = 0; k < 4; ++k) {
            const char* p = pf + ((long)t + (long)k * BTH) * 128;   // 192 KB total
            asm volatile("prefetch.global.L2 [%0];" :: "l"(p));
        }
    }

    // ---- zero ----
    if (t < NW * CC) ((int*)s_hist)[t] = 0;
    for (int i = t; i < CC * DD; i += BTH) s_acc[i] = 0.0f;
    __syncthreads();

    // ---- deterministic counting sort of row indices by label ----
    int mylbl = -1, mypos = 0, myw = t >> 5;
    if (t < NW * 32) {
        mylbl = (t < R) ? labels[(long)bag * NN + rstart + t] : -1;
        unsigned mask = __match_any_sync(0xffffffffu, mylbl);
        int lane = t & 31;
        mypos = __popc(mask & ((1u << lane) - 1u));
        if (mylbl >= 0 && lane == (__ffs(mask) - 1))
            s_hist[myw][mylbl] = __popc(mask);
    }
    __syncthreads();
    if (t < CC) {                               // parallel column sums
        int c = 0;
        #pragma unroll
        for (int w = 0; w < NW; ++w) c += s_hist[w][t];
        s_cnt[t] = c;
    }
    __syncthreads();
    if (t == 0) {                               // short 8-step prefix
        int run = 0;
        #pragma unroll
        for (int l = 0; l < CC; ++l) { s_off[l] = run; run += s_cnt[l]; }
        s_off[CC] = run;
    }
    __syncthreads();
    if (mylbl >= 0) {
        int base = s_off[mylbl];
        #pragma unroll
        for (int w = 0; w < NW; ++w)
            if (w < myw) base += s_hist[w][mylbl];
        s_sorted[base + mypos] = t;             // local row index
    }
    __syncthreads();

    // ---- hot loop: each group walks a contiguous slice of the sorted list ----
    const int g   = t / GTH;                    // 0..3
    const int col = t % GTH;
    const int p0  = (R * g) / GROUPS;
    const int p1  = (R * (g + 1)) / GROUPS;

    const float4* __restrict__ base4 =
        reinterpret_cast<const float4*>(inst) + ((long)bag * NN + rstart) * D4;

    #pragma unroll
    for (int l = 0; l < CC; ++l) {
        int s = s_off[l]     > p0 ? s_off[l]     : p0;
        int e = s_off[l + 1] < p1 ? s_off[l + 1] : p1;
        if (s >= e) continue;

        float4 a0 = make_float4(0.f, 0.f, 0.f, 0.f);
        float4 a1 = make_float4(0.f, 0.f, 0.f, 0.f);
        int j = s;
        for (; j + 2 <= e; j += 2) {            // 4 LDG.128 in flight / thread
            int r0 = s_sorted[j];
            int r1 = s_sorted[j + 1];
            float4 v0 = __ldcs(&base4[(long)r0 * D4 + col]);
            float4 w0 = __ldcs(&base4[(long)r0 * D4 + col + GTH]);
            float4 v1 = __ldcs(&base4[(long)r1 * D4 + col]);
            float4 w1 = __ldcs(&base4[(long)r1 * D4 + col + GTH]);
            a0.x += v0.x; a0.y += v0.y; a0.z += v0.z; a0.w += v0.w;
            a1.x += w0.x; a1.y += w0.y; a1.z += w0.z; a1.w += w0.w;
            a0.x += v1.x; a0.y += v1.y; a0.z += v1.z; a0.w += v1.w;
            a1.x += w1.x; a1.y += w1.y; a1.z += w1.z; a1.w += w1.w;
        }
        if (j < e) {
            int r = s_sorted[j];
            float4 v = __ldcs(&base4[(long)r * D4 + col]);
            float4 w = __ldcs(&base4[(long)r * D4 + col + GTH]);
            a0.x += v.x; a0.y += v.y; a0.z += v.z; a0.w += v.w;
            a1.x += w.x; a1.y += w.y; a1.z += w.z; a1.w += w.w;
        }
        // flush run-partial (<= ~8 flushes per thread total)
        float* d0 = &s_acc[l * DD + col * 4];
        float* d1 = &s_acc[l * DD + (col + GTH) * 4];
        atomicAdd(d0 + 0, a0.x); atomicAdd(d0 + 1, a0.y);
        atomicAdd(d0 + 2, a0.z); atomicAdd(d0 + 3, a0.w);
        atomicAdd(d1 + 0, a1.x); atomicAdd(d1 + 1, a1.y);
        atomicAdd(d1 + 2, a1.z); atomicAdd(d1 + 3, a1.w);
    }
    __syncthreads();

    // ---- epilogue: dot block-partial sums with head_w -> 16 floats ----
    // Each group handles clusters g and g+4.
    {
        const float4* sa = reinterpret_cast<const float4*>(s_acc);
        const float4* W  = reinterpret_cast<const float4*>(head_w);
        float4 u0 = W[col],      u1 = W[col + GTH];        // class 0 row
        float4 v0 = W[D4 + col], v1 = W[D4 + col + GTH];   // class 1 row
        #pragma unroll
        for (int c = g; c < CC; c += GROUPS) {
            float4 a0 = sa[c * D4 + col];
            float4 a1 = sa[c * D4 + col + GTH];
            float l0 = a0.x*u0.x + a0.y*u0.y + a0.z*u0.z + a0.w*u0.w
                     + a1.x*u1.x + a1.y*u1.y + a1.z*u1.z + a1.w*u1.w;
            float l1 = a0.x*v0.x + a0.y*v0.y + a0.z*v0.z + a0.w*v0.w
                     + a1.x*v1.x + a1.y*v1.y + a1.z*v1.z + a1.w*v1.w;
            #pragma unroll
            for (int o = 16; o > 0; o >>= 1) {
                l0 += __shfl_xor_sync(0xffffffff, l0, o);
                l1 += __shfl_xor_sync(0xffffffff, l1, o);
            }
            if ((col & 31) == 0) {
                s_dot[c][col >> 5][0] = l0;
                s_dot[c][col >> 5][1] = l1;
            }
        }
    }
    __syncthreads();
    if (t < CC * NCLS) {                         // 16 threads write logit partials
        int gg = t >> 1, cls = t & 1;
        float s = s_dot[gg][0][cls] + s_dot[gg][1][cls] + s_dot[gg][2][cls];
        g_plog[(blockIdx.x * CC + gg) * NCLS + cls] = s;
    }
    if (t < CC) g_cntp[blockIdx.x * CC + t] = s_cnt[t];

    // ---- last block per bag performs the finalize ----
    __threadfence();                             // publish this block's partials
    __syncthreads();                             // (cumulativity: all writers fenced-before)
    if (t == 0) {
        int old = atomicAdd(&g_bagdone[bag], 1);
        s_isLast = (old == BPB - 1) ? 1 : 0;
    }
    __syncthreads();

    if (s_isLast) {
        const float* plog = g_plog + (long)bag * BPB * CC * NCLS;
        const int*   cntp = g_cntp + (long)bag * BPB * CC;
        for (int i = t; i < BPB * CC * NCLS; i += BTH) s_pl[i] = __ldcg(&plog[i]);
        for (int i = t; i < BPB * CC; i += BTH)        s_pc[i] = __ldcg(&cntp[i]);
        __syncthreads();

        if (t < CC * NCLS) {                     // 16 threads: one (cluster, class)
            int c = t >> 1, cls = t & 1;
            float acc = 0.0f;
            #pragma unroll
            for (int k = 0; k < BPB; ++k) acc += s_pl[(k * CC + c) * NCLS + cls];
            s_logits[c][cls] = acc;
        } else if (t >= 32 && t < 32 + CC) {     // 8 threads: one cluster count
            int c = t - 32;
            int cnt = 0;
            #pragma unroll
            for (int k = 0; k < BPB; ++k) cnt += s_pc[k * CC + c];
            s_ctot[c] = cnt;
        }
        __syncthreads();

        if (t == 0) {
            float b0 = head_b[0], b1 = head_b[1];
            float best = -1e30f, bl0 = 0.f, bl1 = 0.f;
            #pragma unroll
            for (int c = 0; c < CC; ++c) {
                int cnt = s_ctot[c];
                float inv = 1.0f / (float)(cnt > 0 ? cnt : 1);
                float l0 = s_logits[c][0] * inv + b0;
                float l1 = s_logits[c][1] * inv + b1;
                float m  = fmaxf(l0, l1);
                float e0 = expf(l0 - m), e1 = expf(l1 - m);
                float score = 1.0f - e0 / (e0 + e1);   // 1 - p[nor_index=0]
                if (score > best) { best = score; bl0 = l0; bl1 = l1; }
            }
            out[bag * NCLS + 0] = bl0;
            out[bag * NCLS + 1] = bl1;
            g_bagdone[bag] = 0;                  // reset for next graph replay
        }
    }
}

extern "C" void kernel_launch(void* const* d_in, const int* in_sizes, int n_in,
                              void* d_out, int out_size) {
    const float* inst_feat = (const float*)d_in[0];   // [B, N, D] f32
    const int*   labels    = (const int*)  d_in[1];   // [B, N] i32
    const float* head_w    = (const float*)d_in[2];   // [NC, D] f32
    const float* head_b    = (const float*)d_in[3];   // [NC] f32
    float* out = (float*)d_out;                       // [B, NC] f32

    seg_sum_kernel<<<NBLK, BTH>>>(inst_feat, labels, head_w, head_b, out);
}